// round 8
// baseline (speedup 1.0000x reference)
#include <cuda_runtime.h>
#include <cuda_fp16.h>
#include <cstdint>

#define DIM      4096
#define NPAIRS   2048
#define GRD      64
#define P_TILE   8                               // pairs staged per block
#define THREADS  1024
#define SLOTS    4                               // pair-slots (2 pairs each)
#define BSTEP    (THREADS / SLOTS)               // 256 batch rows per iteration
#define GRID_ELEMS (GRD * GRD)                   // 4096 cells per pair
#define GRID_SMEM  (P_TILE * GRID_ELEMS * 4)     // 128 KB (half2 dup-pair cells)
#define DEPTH    4                               // x-ring stages
#define STAGE_BYTES (THREADS * 16)               // 16 KB per stage
#define RING_SMEM  (DEPTH * STAGE_BYTES)         // 64 KB
#define SMEM_BYTES (GRID_SMEM + RING_SMEM)       // 192 KB

__device__ __forceinline__ uint32_t smem_u32(const void* p) {
    return (uint32_t)__cvta_generic_to_shared(p);
}
__device__ __forceinline__ void cp_async16(uint32_t saddr, const void* gptr) {
    asm volatile("cp.async.cg.shared.global [%0], [%1], 16;\n"
                 :: "r"(saddr), "l"(gptr) : "memory");
}
__device__ __forceinline__ void cp_commit() {
    asm volatile("cp.async.commit_group;\n" ::: "memory");
}
__device__ __forceinline__ void cp_wait2() {
    asm volatile("cp.async.wait_group 2;\n" ::: "memory");
}

__global__ void __launch_bounds__(THREADS, 1)
pair_bilinear_kernel(const float* __restrict__ x,
                     const float* __restrict__ pairW,
                     const float* __restrict__ Y,
                     float* __restrict__ out,
                     int b_tile, int bodies)
{
    extern __shared__ __half2 sY[];  // [P_TILE][64][64] dup-pair cells, then x ring
    char* ring = reinterpret_cast<char*>(sY) + GRID_SMEM;

    const int p0 = blockIdx.x * P_TILE;
    const int tid = threadIdx.x;

    // gmem x source base (per-thread 16B slice per stage)
    const int sl  = tid & (SLOTS - 1);           // pair-slot (0..3) -> pairs 2sl,2sl+1
    const int bs  = tid >> 2;                    // batch sub-index (0..255)
    const int pA  = p0 + 2 * sl;                 // first pair of this thread
    const int bstart = blockIdx.y * b_tile + bs;

    const float4* __restrict__ xg =
        reinterpret_cast<const float4*>(x) + (size_t)bstart * (DIM / 4) + (pA >> 1);
    const int XSTR = BSTEP * (DIM / 4);
    const uint32_t ring_base = smem_u32(ring) + tid * 16;

    // ── Prologue: prefetch x stages 0,1 (one commit group per stage) ──────
    cp_async16(ring_base + 0 * STAGE_BYTES, xg);
    cp_commit();
    cp_async16(ring_base + 1 * STAGE_BYTES, xg + (size_t)XSTR);
    cp_commit();

    // ── Stage: duplicated-pair fp16 grid from fp32 Y (overlaps cp.async) ──
    {
        const float4* __restrict__ Yg =
            reinterpret_cast<const float4*>(Y) + p0 * (GRID_ELEMS / 4);
        uint4* __restrict__ sY4 = reinterpret_cast<uint4*>(sY);
        #pragma unroll
        for (int i = tid; i < P_TILE * GRID_ELEMS / 4; i += THREADS) {
            const float4 v = Yg[i];
            const int c4 = i & 15;               // float4 index within 64-wide row
            const float vnext = (c4 < 15) ? *reinterpret_cast<const float*>(Yg + i + 1)
                                          : v.w;  // cell 63 never read
            __half2 h[4];
            h[0] = __floats2half2_rn(v.x, v.y);
            h[1] = __floats2half2_rn(v.y, v.z);
            h[2] = __floats2half2_rn(v.z, v.w);
            h[3] = __floats2half2_rn(v.w, vnext);
            sY4[i] = *reinterpret_cast<const uint4*>(h);   // STS.128, conflict-free
        }
    }

    const float4 wA = *(reinterpret_cast<const float4*>(pairW) + pA);
    const float4 wB = *(reinterpret_cast<const float4*>(pairW) + pA + 1);

    const __half2* __restrict__ sA = sY + (2 * sl) * GRID_ELEMS;
    const __half2* __restrict__ sB = sA + GRID_ELEMS;

    float2* __restrict__ op =
        reinterpret_cast<float2*>(out + (size_t)bstart * NPAIRS + pA);
    const int OSTR = BSTEP * (NPAIRS / 2);

    __syncthreads();   // grid staging complete

    const int iters = bodies * 2;

    // ── Main loop: 2 iterations per body, 8 gather-LDS in flight ─────────
    for (int j = 0; j < bodies; ++j) {
        const int k0 = 2 * j;
        // issue stages k0+2, k0+3 (ring slots are free: consumed at body j-1)
        {
            const int s2 = k0 + 2, s3 = k0 + 3;
            if (s2 < iters)
                cp_async16(ring_base + (s2 & (DEPTH - 1)) * STAGE_BYTES,
                           xg + (size_t)s2 * XSTR);
            cp_commit();
            if (s3 < iters)
                cp_async16(ring_base + (s3 & (DEPTH - 1)) * STAGE_BYTES,
                           xg + (size_t)s3 * XSTR);
            cp_commit();
        }
        cp_wait2();   // stages k0, k0+1 resident

        const float4 xv0 = *reinterpret_cast<const float4*>(
            ring + ((k0)     & (DEPTH - 1)) * STAGE_BYTES + tid * 16);
        const float4 xv1 = *reinterpret_cast<const float4*>(
            ring + ((k0 + 1) & (DEPTH - 1)) * STAGE_BYTES + tid * 16);

        // ---- addresses for both iterations, then all 8 gathers ----
        // iter 0
        const float a00 = fmaf(xv0.x, wA.x, xv0.y * wA.z);
        const float a01 = fmaf(xv0.x, wA.y, xv0.y * wA.w);
        const float b00 = fmaf(xv0.z, wB.x, xv0.w * wB.z);
        const float b01 = fmaf(xv0.z, wB.y, xv0.w * wB.w);
        const float gA00 = fminf(fmaxf(a00 * 63.0f, 0.0f), 63.0f);
        const float gA01 = fminf(fmaxf(a01 * 63.0f, 0.0f), 63.0f);
        const float gB00 = fminf(fmaxf(b00 * 63.0f, 0.0f), 63.0f);
        const float gB01 = fminf(fmaxf(b01 * 63.0f, 0.0f), 63.0f);
        const int rA0 = min((int)gA00, 62), cA0 = min((int)gA01, 62);
        const int rB0 = min((int)gB00, 62), cB0 = min((int)gB01, 62);
        const float frA0 = gA00 - (float)rA0, fcA0 = gA01 - (float)cA0;
        const float frB0 = gB00 - (float)rB0, fcB0 = gB01 - (float)cB0;
        const int baseA0 = (rA0 << 6) + cA0;
        const int baseB0 = (rB0 << 6) + cB0;
        // iter 1
        const float a10 = fmaf(xv1.x, wA.x, xv1.y * wA.z);
        const float a11 = fmaf(xv1.x, wA.y, xv1.y * wA.w);
        const float b10 = fmaf(xv1.z, wB.x, xv1.w * wB.z);
        const float b11 = fmaf(xv1.z, wB.y, xv1.w * wB.w);
        const float gA10 = fminf(fmaxf(a10 * 63.0f, 0.0f), 63.0f);
        const float gA11 = fminf(fmaxf(a11 * 63.0f, 0.0f), 63.0f);
        const float gB10 = fminf(fmaxf(b10 * 63.0f, 0.0f), 63.0f);
        const float gB11 = fminf(fmaxf(b11 * 63.0f, 0.0f), 63.0f);
        const int rA1 = min((int)gA10, 62), cA1 = min((int)gA11, 62);
        const int rB1 = min((int)gB10, 62), cB1 = min((int)gB11, 62);
        const float frA1 = gA10 - (float)rA1, fcA1 = gA11 - (float)cA1;
        const float frB1 = gB10 - (float)rB1, fcB1 = gB11 - (float)cB1;
        const int baseA1 = (rA1 << 6) + cA1;
        const int baseB1 = (rB1 << 6) + cB1;

        // 8 independent gather LDS, all in flight before any consume
        const __half2 tA0 = sA[baseA0], bA0 = sA[baseA0 + GRD];
        const __half2 tB0 = sB[baseB0], bB0 = sB[baseB0 + GRD];
        const __half2 tA1 = sA[baseA1], bA1 = sA[baseA1 + GRD];
        const __half2 tB1 = sB[baseB1], bB1 = sB[baseB1 + GRD];

        // ---- blends + stores ----
        {
            const float2 ta = __half22float2(tA0);
            const float2 ba = __half22float2(bA0);
            const float2 tb = __half22float2(tB0);
            const float2 bb = __half22float2(bB0);
            const float topA = fmaf(fcA0, ta.y - ta.x, ta.x);
            const float botA = fmaf(fcA0, ba.y - ba.x, ba.x);
            const float topB = fmaf(fcB0, tb.y - tb.x, tb.x);
            const float botB = fmaf(fcB0, bb.y - bb.x, bb.x);
            float2 o;
            o.x = fmaf(frA0, botA - topA, topA);
            o.y = fmaf(frB0, botB - topB, topB);
            __stcs(op, o);
        }
        {
            const float2 ta = __half22float2(tA1);
            const float2 ba = __half22float2(bA1);
            const float2 tb = __half22float2(tB1);
            const float2 bb = __half22float2(bB1);
            const float topA = fmaf(fcA1, ta.y - ta.x, ta.x);
            const float botA = fmaf(fcA1, ba.y - ba.x, ba.x);
            const float topB = fmaf(fcB1, tb.y - tb.x, tb.x);
            const float botB = fmaf(fcB1, bb.y - bb.x, bb.x);
            float2 o;
            o.x = fmaf(frA1, botA - topA, topA);
            o.y = fmaf(frB1, botB - topB, topB);
            __stcs(op + OSTR, o);
        }
        op += 2 * OSTR;
    }
}

extern "C" void kernel_launch(void* const* d_in, const int* in_sizes, int n_in,
                              void* d_out, int out_size)
{
    const float* x     = (const float*)d_in[0];
    const float* pairW = (const float*)d_in[1];
    const float* Y     = (const float*)d_in[2];
    float* out         = (float*)d_out;

    const int batch = in_sizes[0] / DIM;   // 8192

    const int b_blocks = 4;
    const int b_tile = batch / b_blocks;                 // 2048
    const int bodies = b_tile / (2 * BSTEP);             // 4

    cudaFuncSetAttribute(pair_bilinear_kernel,
                         cudaFuncAttributeMaxDynamicSharedMemorySize, SMEM_BYTES);

    dim3 grid(NPAIRS / P_TILE, b_blocks);   // (256, 4) = 1024 blocks
    pair_bilinear_kernel<<<grid, THREADS, SMEM_BYTES>>>(x, pairW, Y, out, b_tile, bodies);
}